// round 9
// baseline (speedup 1.0000x reference)
#include <cuda_runtime.h>
#include <cstdint>

// RoIAlign (torchvision, aligned=false), POOLED=7, SCALE=1, SR=2.
// features: [2,256,200,200] f32, rois: [512,5] f32, out: [512,256,7,7] f32
//
// R9: R8 gather core (warp = bin-row, lane = pw*4+sample, shfl_xor(1,2),
// unpredicated loads) with:
//  - CCHUNK=8 as ONE straight-line body: 32 LDG issued before first use
//    (true deep MLP; R7's loop version was re-serialized at 32 regs).
//  - __launch_bounds__(224, 6): reg budget ~42 so the batch survives.
//  - CSPLIT=32 -> 16384 blocks: tail-wave idle < 1%.

#define CCH    256
#define HH     200
#define WW     200
#define PP     7
#define KROIS  512
#define NBINS  (PP * PP)        // 49
#define NSAMP  (NBINS * 4)      // 196
#define PLANE  (HH * WW)        // 40000
#define CSPLIT 32
#define CCHUNK (CCH / CSPLIT)   // 8
#define TPB    224              // 7 warps
#define UNR    8                // = CCHUNK, fully unrolled straight-line

__global__ __launch_bounds__(TPB, 6)
void roi_align_kernel(const float* __restrict__ feat,
                      const float* __restrict__ rois,
                      float* __restrict__ out)
{
    __shared__ int    s_off[NSAMP];     // [pp*4 + s]
    __shared__ float4 s_w[NSAMP];       // [pp*4 + s]
    __shared__ int    s_b;

    const int k     = blockIdx.x;
    const int cbase = blockIdx.y * CCHUNK;
    const int tid   = threadIdx.x;

    // --- per-ROI sample table (layout [pp][s]) -------------------------
    const float r0 = rois[k * 5 + 0];
    const float x1 = rois[k * 5 + 1];
    const float y1 = rois[k * 5 + 2];
    const float x2 = rois[k * 5 + 3];
    const float y2 = rois[k * 5 + 4];

    const float roi_w = fmaxf(x2 - x1, 1.0f);
    const float roi_h = fmaxf(y2 - y1, 1.0f);
    const float bin_w = roi_w * (1.0f / PP);
    const float bin_h = roi_h * (1.0f / PP);

    if (tid == 0) s_b = (int)r0;

    if (tid < NSAMP) {
        const int pp = tid >> 2;         // bin 0..48 (ph*7+pw)
        const int s  = tid & 3;          // sample 0..3 (sy*2+sx)
        const int ph = pp / PP;
        const int pw = pp - ph * PP;
        const int sy = s >> 1;
        const int sx = s & 1;

        const float gy = (float)ph + ((float)sy + 0.5f) * 0.5f;
        const float gx = (float)pw + ((float)sx + 0.5f) * 0.5f;
        float y = y1 + gy * bin_h;
        float x = x1 + gx * bin_w;

        const bool valid = (y >= -1.0f) && (y <= (float)HH) &&
                           (x >= -1.0f) && (x <= (float)WW);

        y = fminf(fmaxf(y, 0.0f), (float)(HH - 1));
        x = fminf(fmaxf(x, 0.0f), (float)(WW - 1));

        int y0 = (int)floorf(y); if (y0 > HH - 2) y0 = HH - 2;
        int x0 = (int)floorf(x); if (x0 > WW - 2) x0 = WW - 2;

        const float ly = y - (float)y0;
        const float lx = x - (float)x0;
        const float hy = 1.0f - ly;
        const float hx = 1.0f - lx;
        const float vs = valid ? 0.25f : 0.0f;   // fold mean(1/4) + validity

        s_off[tid] = y0 * WW + x0;
        s_w[tid]   = make_float4(hy * hx * vs, hy * lx * vs,
                                 ly * hx * vs, ly * lx * vs);
    }
    __syncthreads();

    const int warp = tid >> 5;           // 0..6 = bin-row ph
    const int lane = tid & 31;
    const bool act = (lane < 28);
    const int pp   = warp * PP + (act ? (lane >> 2) : 6);
    const int si   = pp * 4 + (lane & 3);

    const int    o = s_off[si];
    const float4 w = s_w[si];

    const float* __restrict__ p  = feat + (size_t)s_b * (CCH * PLANE)
                                        + (size_t)cbase * PLANE + o;
    float* __restrict__        ob = out  + (size_t)k * (CCH * NBINS)
                                        + (size_t)cbase * NBINS + pp;

    const bool wr = act && ((lane & 3) == 0);

    // --- straight-line body: 8 channels, 32 unpredicated gathers -------
    float a[UNR], b[UNR], cc[UNR], d[UNR];
    #pragma unroll
    for (int j = 0; j < UNR; ++j) {
        a[j]  = p[j * PLANE];
        b[j]  = p[j * PLANE + 1];
        cc[j] = p[j * PLANE + WW];
        d[j]  = p[j * PLANE + WW + 1];
    }

    float v[UNR];
    #pragma unroll
    for (int j = 0; j < UNR; ++j)
        v[j] = w.x * a[j] + w.y * b[j] + w.z * cc[j] + w.w * d[j];

    #pragma unroll
    for (int j = 0; j < UNR; ++j)
        v[j] += __shfl_xor_sync(0xFFFFFFFFu, v[j], 1);
    #pragma unroll
    for (int j = 0; j < UNR; ++j)
        v[j] += __shfl_xor_sync(0xFFFFFFFFu, v[j], 2);

    if (wr) {
        #pragma unroll
        for (int j = 0; j < UNR; ++j)
            ob[(size_t)j * NBINS] = v[j];
    }
}

extern "C" void kernel_launch(void* const* d_in, const int* in_sizes, int n_in,
                              void* d_out, int out_size)
{
    const float* feat = (const float*)d_in[0];
    const float* rois = (const float*)d_in[1];
    float*       out  = (float*)d_out;

    dim3 grid(KROIS, CSPLIT);
    roi_align_kernel<<<grid, TPB>>>(feat, rois, out);
}

// round 12
// speedup vs baseline: 1.1406x; 1.1406x over previous
#include <cuda_runtime.h>
#include <cstdint>

// RoIAlign (torchvision, aligned=false), POOLED=7, SCALE=1, SR=2.
// features: [2,256,200,200] f32, rois: [512,5] f32, out: [512,256,7,7] f32
//
// R10 (3rd submit; prior two runs died to broker/container infra failures,
// not kernel errors): R8 gather core (warp = bin-row, lane = pw*4+sample,
// shfl_xor(1,2), unroll x4, unpredicated loads, CSPLIT=16) with the
// shared-memory sample table ELIMINATED: each lane computes its own
// (offset, weights) directly in registers. No smem, no STS/LDS, no
// __syncthreads.

#define CCH    256
#define HH     200
#define WW     200
#define PP     7
#define KROIS  512
#define NBINS  (PP * PP)        // 49
#define PLANE  (HH * WW)        // 40000
#define CSPLIT 16
#define CCHUNK (CCH / CSPLIT)   // 16
#define TPB    224              // 7 warps
#define UNR    4

__global__ __launch_bounds__(TPB, 9)
void roi_align_kernel(const float* __restrict__ feat,
                      const float* __restrict__ rois,
                      float* __restrict__ out)
{
    const int k     = blockIdx.x;
    const int cbase = blockIdx.y * CCHUNK;
    const int tid   = threadIdx.x;

    const int warp = tid >> 5;           // 0..6 = bin-row ph
    const int lane = tid & 31;
    const bool act = (lane < 28);
    const int pwv  = act ? (lane >> 2) : 6;   // idle lanes mirror bin 6
    const int pp   = warp * PP + pwv;
    const int s    = lane & 3;           // sample (sy*2+sx)

    // --- per-lane sample point, fully in registers ---------------------
    const float r0 = rois[k * 5 + 0];    // broadcast loads (1 wf each)
    const float x1 = rois[k * 5 + 1];
    const float y1 = rois[k * 5 + 2];
    const float x2 = rois[k * 5 + 3];
    const float y2 = rois[k * 5 + 4];

    const float roi_w = fmaxf(x2 - x1, 1.0f);
    const float roi_h = fmaxf(y2 - y1, 1.0f);
    const float bin_w = roi_w * (1.0f / PP);
    const float bin_h = roi_h * (1.0f / PP);

    const int sy = s >> 1;
    const int sx = s & 1;

    const float gy = (float)warp + ((float)sy + 0.5f) * 0.5f;
    const float gx = (float)pwv  + ((float)sx + 0.5f) * 0.5f;
    float y = y1 + gy * bin_h;
    float x = x1 + gx * bin_w;

    const bool valid = (y >= -1.0f) && (y <= (float)HH) &&
                       (x >= -1.0f) && (x <= (float)WW);

    y = fminf(fmaxf(y, 0.0f), (float)(HH - 1));
    x = fminf(fmaxf(x, 0.0f), (float)(WW - 1));

    int y0 = (int)floorf(y); if (y0 > HH - 2) y0 = HH - 2;
    int x0 = (int)floorf(x); if (x0 > WW - 2) x0 = WW - 2;

    const float ly = y - (float)y0;
    const float lx = x - (float)x0;
    const float hy = 1.0f - ly;
    const float hx = 1.0f - lx;
    const float vs = valid ? 0.25f : 0.0f;       // fold mean(1/4) + validity

    const float wxx = hy * hx * vs;
    const float wxy = hy * lx * vs;
    const float wzx = ly * hx * vs;
    const float wzy = ly * lx * vs;

    const int o = y0 * WW + x0;

    const float* __restrict__ fbase = feat + (size_t)(int)r0 * (CCH * PLANE)
                                           + (size_t)cbase * PLANE + o;
    float* __restrict__        ob   = out  + (size_t)k * (CCH * NBINS)
                                           + (size_t)cbase * NBINS + pp;

    const bool wr = act && (s == 0);

    #pragma unroll 1
    for (int c = 0; c < CCHUNK; c += UNR) {
        const float* p = fbase + (size_t)c * PLANE;

        // 16 independent, unpredicated gathers (idle lanes dup bin 6).
        float a[UNR], b[UNR], cc[UNR], d[UNR];
        #pragma unroll
        for (int j = 0; j < UNR; ++j) {
            a[j]  = p[j * PLANE];
            b[j]  = p[j * PLANE + 1];
            cc[j] = p[j * PLANE + WW];
            d[j]  = p[j * PLANE + WW + 1];
        }

        float v[UNR];
        #pragma unroll
        for (int j = 0; j < UNR; ++j)
            v[j] = wxx * a[j] + wxy * b[j] + wzx * cc[j] + wzy * d[j];

        #pragma unroll
        for (int j = 0; j < UNR; ++j)
            v[j] += __shfl_xor_sync(0xFFFFFFFFu, v[j], 1);
        #pragma unroll
        for (int j = 0; j < UNR; ++j)
            v[j] += __shfl_xor_sync(0xFFFFFFFFu, v[j], 2);

        if (wr) {
            #pragma unroll
            for (int j = 0; j < UNR; ++j)
                ob[(size_t)(c + j) * NBINS] = v[j];
        }
    }
}

extern "C" void kernel_launch(void* const* d_in, const int* in_sizes, int n_in,
                              void* d_out, int out_size)
{
    const float* feat = (const float*)d_in[0];
    const float* rois = (const float*)d_in[1];
    float*       out  = (float*)d_out;

    dim3 grid(KROIS, CSPLIT);
    roi_align_kernel<<<grid, TPB>>>(feat, rois, out);
}